// round 16
// baseline (speedup 1.0000x reference)
#include <cuda_runtime.h>
#include <math.h>

// Problem dims (fixed by the dataset)
#define Bn   4
#define Cn   256
#define HWn  65536
#define Pn   256
#define THRESH_F 0.8f
#define EPSn 1e-5f

typedef unsigned long long ull;

// ---------------------------------------------------------------------------
// Scratch (no cudaMalloc). All state reset in-kernel for graph replay.
// ---------------------------------------------------------------------------
__device__ __align__(16) int   g_idx[Bn * Pn];
__device__ __align__(16) float g_feat[Bn * Pn * Cn];   // (B, P, C)
__device__ __align__(16) float g_z[Bn * Pn * Cn];      // (B, P, C)
__device__ __align__(16) float g_z2[Bn * Pn * Cn];     // (B, P, C)

__device__ unsigned int g_hist[3][Bn][65536];    // zero at rest
__device__ unsigned int g_coarse[3][Bn][1024];   // zero at rest
__device__ ull g_prefix[Bn];                     // zero at rest
__device__ int g_K[Bn] = {Pn, Pn, Pn, Pn};       // Pn at rest
__device__ int g_candcnt[Bn];                    // zero at rest
__device__ ull g_cand[Bn][Pn];
__device__ volatile unsigned int g_bar[Bn][12];  // zero at rest
__device__ volatile unsigned int g_copydone;     // zero at rest
__device__ unsigned int g_scatdone;              // zero at rest

#define NSIDE 64                 // 16 side CTAs per batch
#define NCOPY 232
#define NTOT  (NSIDE + NCOPY)    // 296 = 2 CTAs/SM x 148 -> all co-resident
#define NBLK  16

// ---------------------------------------------------------------------------
// 48-bit composite key: (monotone_float32 << 16) | (0xFFFF - idx)
// ---------------------------------------------------------------------------
__device__ __forceinline__ ull make_key(float e, int i) {
    float v = (e < THRESH_F) ? 0.0f : e;
    unsigned int ub = __float_as_uint(v);
    ub = (ub & 0x80000000u) ? ~ub : (ub | 0x80000000u);
    return ((ull)ub << 16) | (ull)(0xFFFFu - (unsigned int)i);
}

// Per-batch spin barrier over the NBLK side CTAs of batch b.
__device__ __forceinline__ void batch_barrier(int b, int slot) {
    __threadfence();
    __syncthreads();
    if (threadIdx.x == 0) {
        atomicAdd((unsigned int*)&g_bar[b][slot], 1u);
        while (g_bar[b][slot] < NBLK) { }
        __threadfence();
    }
    __syncthreads();
}

// ---------------------------------------------------------------------------
// MEGA KERNEL: CTAs 0..NSIDE-1: topk+gather+GEMM1+GEMM2, wait for copy,
// scatter. CTAs NSIDE..: copy with EXPLICIT 8-deep load batching (MLP=8
// per thread: all 8 LDG.128 in flight before any STG) + streaming hints.
// ---------------------------------------------------------------------------
__global__ void __launch_bounds__(512, 2)
mega_kernel(const float4* __restrict__ xv, float4* __restrict__ outv,
            const float* __restrict__ x,
            const float* __restrict__ edge,
            const float* __restrict__ W,
            const float* __restrict__ ga, const float* __restrict__ ba,
            const float* __restrict__ ma, const float* __restrict__ va,
            const float* __restrict__ Wg,
            const float* __restrict__ gw, const float* __restrict__ bw,
            const float* __restrict__ mw, const float* __restrict__ vw,
            float* __restrict__ out) {
    const int blk = blockIdx.x;
    const int t   = threadIdx.x;

    // ======================= COPY ROLE =======================
    if (blk >= NSIDE) {
        const int n4 = Bn * Cn * HWn / 4;     // 16,777,216 float4
        const int stride = NCOPY * 512;       // 118,784
        int i = (blk - NSIDE) * 512 + t;

        // Batched main loop: 8 independent loads in flight before stores.
        for (; i + 7 * stride < n4; i += 8 * stride) {
            const float4 v0 = __ldcs(&xv[i + 0 * stride]);
            const float4 v1 = __ldcs(&xv[i + 1 * stride]);
            const float4 v2 = __ldcs(&xv[i + 2 * stride]);
            const float4 v3 = __ldcs(&xv[i + 3 * stride]);
            const float4 v4 = __ldcs(&xv[i + 4 * stride]);
            const float4 v5 = __ldcs(&xv[i + 5 * stride]);
            const float4 v6 = __ldcs(&xv[i + 6 * stride]);
            const float4 v7 = __ldcs(&xv[i + 7 * stride]);
            __stcs(&outv[i + 0 * stride], v0);
            __stcs(&outv[i + 1 * stride], v1);
            __stcs(&outv[i + 2 * stride], v2);
            __stcs(&outv[i + 3 * stride], v3);
            __stcs(&outv[i + 4 * stride], v4);
            __stcs(&outv[i + 5 * stride], v5);
            __stcs(&outv[i + 6 * stride], v6);
            __stcs(&outv[i + 7 * stride], v7);
        }
        // Remainder.
        for (; i < n4; i += stride) __stcs(&outv[i], __ldcs(&xv[i]));

        __threadfence();
        __syncthreads();
        if (t == 0) atomicAdd((unsigned int*)&g_copydone, 1u);
        return;
    }

    // ======================= SIDE ROLE =======================
    const int b   = blk >> 4;
    const int sub = blk & 15;
    const int lane = t & 31;
    const int w    = t >> 5;

    __shared__ unsigned int warpsum[16];
    __shared__ unsigned int warpsuf[16];
    __shared__ int sh_cbin;
    __shared__ unsigned int sh_krem;
    __shared__ unsigned int bins[64];
    __shared__ ull skeys[Pn];
    __shared__ __align__(16) float sA[2][32][65];
    __shared__ __align__(16) float sB[2][32][68];

    // ---- keys in registers (8/thread) ----
    const int ibase = sub * 4096 + t * 8;
    const float4 e0 = *(const float4*)&edge[(size_t)b * HWn + ibase];
    const float4 e1 = *(const float4*)&edge[(size_t)b * HWn + ibase + 4];
    ull key[8];
    key[0] = make_key(e0.x, ibase + 0); key[1] = make_key(e0.y, ibase + 1);
    key[2] = make_key(e0.z, ibase + 2); key[3] = make_key(e0.w, ibase + 3);
    key[4] = make_key(e1.x, ibase + 4); key[5] = make_key(e1.y, ibase + 5);
    key[6] = make_key(e1.z, ibase + 6); key[7] = make_key(e1.w, ibase + 7);

    int slot = 0;
    #pragma unroll
    for (int pass = 2; pass >= 0; --pass) {
        const ull pre = (pass == 2) ? 0ull : *(volatile ull*)&g_prefix[b];
        #pragma unroll
        for (int j = 0; j < 8; ++j) {
            const bool active = (pass == 2) ||
                                ((key[j] >> ((pass + 1) * 16)) == pre);
            const unsigned int bin =
                (unsigned int)((key[j] >> (pass * 16)) & 0xFFFFull);
            const unsigned int amask = __ballot_sync(0xFFFFFFFFu, active);
            if (active) {
                unsigned int peers = __match_any_sync(amask, bin);
                if (lane == __ffs(peers) - 1)
                    atomicAdd(&g_hist[pass][b][bin], (unsigned int)__popc(peers));
                unsigned int peersc = __match_any_sync(amask, bin >> 6);
                if (lane == __ffs(peersc) - 1)
                    atomicAdd(&g_coarse[pass][b][bin >> 6], (unsigned int)__popc(peersc));
            }
        }

        batch_barrier(b, slot++);

        if (sub == 0) {
            const unsigned int c0 = g_coarse[pass][b][2 * t];
            const unsigned int c1 = g_coarse[pass][b][2 * t + 1];
            const unsigned int mine = c0 + c1;

            unsigned int suf = mine;
            #pragma unroll
            for (int off = 1; off < 32; off <<= 1) {
                const unsigned int v = __shfl_down_sync(0xFFFFFFFFu, suf, off);
                if (lane + off < 32) suf += v;
            }
            if (lane == 0) warpsum[w] = suf;
            __syncthreads();

            if (w == 0) {
                const unsigned int ws = (lane < 16) ? warpsum[lane] : 0u;
                unsigned int wsuf = ws;
                #pragma unroll
                for (int off = 1; off < 32; off <<= 1) {
                    const unsigned int v = __shfl_down_sync(0xFFFFFFFFu, wsuf, off);
                    if (lane + off < 32) wsuf += v;
                }
                if (lane < 16) warpsuf[lane] = wsuf - ws;
            }
            __syncthreads();

            const unsigned int K = (unsigned int)g_K[b];
            const unsigned int suf_t = suf + warpsuf[w];
            const unsigned int above = suf_t - mine;
            if (suf_t >= K && above < K) {
                const unsigned int kp = K - above;
                if (kp <= c1) { sh_cbin = 2 * t + 1; sh_krem = kp; }
                else          { sh_cbin = 2 * t;     sh_krem = kp - c1; }
            }
            __syncthreads();

            const int cbin = sh_cbin;
            if (t < 64) bins[t] = g_hist[pass][b][cbin * 64 + t];
            __syncthreads();

            if (w == 0) {
                const unsigned int krem = sh_krem;
                const unsigned int lo = bins[lane];
                const unsigned int hi = bins[lane + 32];

                unsigned int suf_hi = hi;
                #pragma unroll
                for (int off = 1; off < 32; off <<= 1) {
                    const unsigned int v = __shfl_down_sync(0xFFFFFFFFu, suf_hi, off);
                    if (lane + off < 32) suf_hi += v;
                }
                const unsigned int hi_total = __shfl_sync(0xFFFFFFFFu, suf_hi, 0);

                unsigned int suf_lo = lo;
                #pragma unroll
                for (int off = 1; off < 32; off <<= 1) {
                    const unsigned int v = __shfl_down_sync(0xFFFFFFFFu, suf_lo, off);
                    if (lane + off < 32) suf_lo += v;
                }
                suf_lo += hi_total;

                { const unsigned int st = suf_hi, ab = st - hi;
                  if (st >= krem && ab < krem) {
                      g_prefix[b] = (g_prefix[b] << 16) | (ull)(cbin * 64 + 32 + lane);
                      g_K[b] = (int)(krem - ab);
                  } }
                { const unsigned int st = suf_lo, ab = st - lo;
                  if (st >= krem && ab < krem) {
                      g_prefix[b] = (g_prefix[b] << 16) | (ull)(cbin * 64 + lane);
                      g_K[b] = (int)(krem - ab);
                  } }
            }
            __syncthreads();
        }

        batch_barrier(b, slot++);
    }

    // ---- collect ----
    const ull cutoff = *(volatile ull*)&g_prefix[b];
    #pragma unroll
    for (int j = 0; j < 8; ++j) {
        if (key[j] >= cutoff) {
            const int p = atomicAdd(&g_candcnt[b], 1);
            if (p < Pn) g_cand[b][p] = key[j];
        }
    }

    batch_barrier(b, slot++);   // slot 6

    // ---- restore histograms; sub 0 sorts + emits indices ----
    {
        const int base = sub * 512 + t;
        #pragma unroll
        for (int p = 0; p < 3; ++p) {
            #pragma unroll
            for (int r = 0; r < 8; ++r)
                g_hist[p][b][base + r * 8192] = 0u;
            if (base < 1024) g_coarse[p][b][base] = 0u;
        }
    }
    if (sub == 0) {
        if (t < Pn) skeys[t] = g_cand[b][t];
        __syncthreads();
        for (int kk = 2; kk <= Pn; kk <<= 1) {
            for (int jj = kk >> 1; jj > 0; jj >>= 1) {
                if (t < Pn) {
                    const int ixj = t ^ jj;
                    if (ixj > t) {
                        const ull a = skeys[t];
                        const ull c = skeys[ixj];
                        const bool up = ((t & kk) == 0);
                        if (up ? (a < c) : (a > c)) { skeys[t] = c; skeys[ixj] = a; }
                    }
                }
                __syncthreads();
            }
        }
        if (t < Pn)
            g_idx[b * Pn + t] = (int)(0xFFFFu - (unsigned int)(skeys[t] & 0xFFFFull));
        if (t == 0) {
            g_candcnt[b] = 0;
            g_prefix[b] = 0ull;
            g_K[b] = Pn;
        }
    }

    batch_barrier(b, slot++);   // slot 7: g_idx ready

    // ---- gather: n-rows [sub*16, sub*16+16) ----
    {
        float* F = g_feat + b * Pn * Cn;
        const int n  = sub * 16 + (t >> 5);
        const int d0 = lane * 8;
        const int col = g_idx[b * Pn + n];
        const float* xp = x + (size_t)b * Cn * HWn + col;
        float4 v0, v1;
        v0.x = xp[(size_t)(d0 + 0) * HWn];
        v0.y = xp[(size_t)(d0 + 1) * HWn];
        v0.z = xp[(size_t)(d0 + 2) * HWn];
        v0.w = xp[(size_t)(d0 + 3) * HWn];
        v1.x = xp[(size_t)(d0 + 4) * HWn];
        v1.y = xp[(size_t)(d0 + 5) * HWn];
        v1.z = xp[(size_t)(d0 + 6) * HWn];
        v1.w = xp[(size_t)(d0 + 7) * HWn];
        *(float4*)&F[n * Cn + d0]     = v0;
        *(float4*)&F[n * Cn + d0 + 4] = v1;
    }

    batch_barrier(b, slot++);   // slot 8: F ready

    const int ti = (sub >> 2) * 64;
    const int td = (sub & 3) * 64;
    const int tx = t & 15;
    const int ty = t >> 4;

    // ---- GEMM1 (64x64, KB=32, double-buffered) ----
    {
        const float* F = g_feat + b * Pn * Cn;
        float* Z       = g_z    + b * Pn * Cn;
        const int ai = t >> 3, ak = (t & 7) * 4;
        const int bk = t >> 4, bd = (t & 15) * 4;

        float4 na, nb;
        float acc[2][4] = {};

        na = *(const float4*)&W[(ti + ai) * Pn + ak];
        nb = *(const float4*)&F[bk * Cn + td + bd];
        sA[0][ak + 0][ai] = na.x; sA[0][ak + 1][ai] = na.y;
        sA[0][ak + 2][ai] = na.z; sA[0][ak + 3][ai] = na.w;
        *(float4*)&sB[0][bk][bd] = nb;
        __syncthreads();

        #pragma unroll
        for (int kt = 0; kt < 8; ++kt) {
            const int st = kt & 1;
            if (kt < 7) {
                const int k0 = (kt + 1) * 32;
                na = *(const float4*)&W[(ti + ai) * Pn + k0 + ak];
                nb = *(const float4*)&F[(k0 + bk) * Cn + td + bd];
            }
            #pragma unroll
            for (int k = 0; k < 32; ++k) {
                const float a0 = sA[st][k][ty * 2 + 0];
                const float a1 = sA[st][k][ty * 2 + 1];
                const float4 b4 = *(const float4*)&sB[st][k][tx * 4];
                acc[0][0] += a0 * b4.x; acc[0][1] += a0 * b4.y;
                acc[0][2] += a0 * b4.z; acc[0][3] += a0 * b4.w;
                acc[1][0] += a1 * b4.x; acc[1][1] += a1 * b4.y;
                acc[1][2] += a1 * b4.z; acc[1][3] += a1 * b4.w;
            }
            if (kt < 7) {
                const int sn = st ^ 1;
                sA[sn][ak + 0][ai] = na.x; sA[sn][ak + 1][ai] = na.y;
                sA[sn][ak + 2][ai] = na.z; sA[sn][ak + 3][ai] = na.w;
                *(float4*)&sB[sn][bk][bd] = nb;
            }
            __syncthreads();
        }

        const int d = td + tx * 4;
        #pragma unroll
        for (int ui = 0; ui < 2; ++ui) {
            const int i = ti + ty * 2 + ui;
            const float inv = ga[i] * rsqrtf(va[i] + EPSn);
            const float add = ba[i] - ma[i] * inv;
            const float4 f4 = *(const float4*)&F[i * Cn + d];
            float4 o;
            o.x = fmaxf(acc[ui][0] * inv + add, 0.0f) + f4.x;
            o.y = fmaxf(acc[ui][1] * inv + add, 0.0f) + f4.y;
            o.z = fmaxf(acc[ui][2] * inv + add, 0.0f) + f4.z;
            o.w = fmaxf(acc[ui][3] * inv + add, 0.0f) + f4.w;
            *(float4*)&Z[i * Cn + d] = o;
        }
    }

    batch_barrier(b, slot++);   // slot 9: Z ready

    // ---- GEMM2 (NT, 64x64, KB=32, double-buffered) ----
    {
        const float* Z = g_z  + b * Pn * Cn;
        float* Z2      = g_z2 + b * Pn * Cn;
        const int ar = t >> 3, ak = (t & 7) * 4;

        float4 na, nb;
        float acc[2][4] = {};

        na = *(const float4*)&Z[(ti + ar) * Cn + ak];
        nb = *(const float4*)&Wg[(td + ar) * Cn + ak];
        sA[0][ak + 0][ar] = na.x; sA[0][ak + 1][ar] = na.y;
        sA[0][ak + 2][ar] = na.z; sA[0][ak + 3][ar] = na.w;
        sB[0][ak + 0][ar] = nb.x; sB[0][ak + 1][ar] = nb.y;
        sB[0][ak + 2][ar] = nb.z; sB[0][ak + 3][ar] = nb.w;
        __syncthreads();

        #pragma unroll
        for (int kt = 0; kt < 8; ++kt) {
            const int st = kt & 1;
            if (kt < 7) {
                const int k0 = (kt + 1) * 32;
                na = *(const float4*)&Z[(ti + ar) * Cn + k0 + ak];
                nb = *(const float4*)&Wg[(td + ar) * Cn + k0 + ak];
            }
            #pragma unroll
            for (int k = 0; k < 32; ++k) {
                const float a0 = sA[st][k][ty * 2 + 0];
                const float a1 = sA[st][k][ty * 2 + 1];
                const float4 b4 = *(const float4*)&sB[st][k][tx * 4];
                acc[0][0] += a0 * b4.x; acc[0][1] += a0 * b4.y;
                acc[0][2] += a0 * b4.z; acc[0][3] += a0 * b4.w;
                acc[1][0] += a1 * b4.x; acc[1][1] += a1 * b4.y;
                acc[1][2] += a1 * b4.z; acc[1][3] += a1 * b4.w;
            }
            if (kt < 7) {
                const int sn = st ^ 1;
                sA[sn][ak + 0][ar] = na.x; sA[sn][ak + 1][ar] = na.y;
                sA[sn][ak + 2][ar] = na.z; sA[sn][ak + 3][ar] = na.w;
                sB[sn][ak + 0][ar] = nb.x; sB[sn][ak + 1][ar] = nb.y;
                sB[sn][ak + 2][ar] = nb.z; sB[sn][ak + 3][ar] = nb.w;
            }
            __syncthreads();
        }

        #pragma unroll
        for (int uc = 0; uc < 4; ++uc) {
            const int c = td + tx * 4 + uc;
            const float inv = gw[c] * rsqrtf(vw[c] + EPSn);
            const float add = bw[c] - mw[c] * inv;
            #pragma unroll
            for (int ui = 0; ui < 2; ++ui) {
                const int p = ti + ty * 2 + ui;
                Z2[p * Cn + c] = fmaxf(acc[ui][uc] * inv + add, 0.0f);
            }
        }
    }

    batch_barrier(b, slot++);   // slot 10: z2 fully written (this batch)

    // ---- wait until the whole copy is complete ----
    if (t == 0) {
        while (g_copydone < NCOPY) { }
        __threadfence();
    }
    __syncthreads();

    // ---- scatter: out[b, c, idx[b,p]] = z2[b,p,c] for p in [sub*16, +16) ----
    {
        const float* Z2 = g_z2 + b * Pn * Cn;
        const int p   = sub * 16 + (t >> 5);
        const int col = g_idx[b * Pn + p];
        float* op = out + (size_t)b * Cn * HWn + col;
        #pragma unroll
        for (int k = 0; k < 8; ++k) {
            const int c = lane + k * 32;
            op[(size_t)c * HWn] = Z2[p * Cn + c];
        }
    }

    // ---- last scatterer resets all replay state ----
    __threadfence();
    __syncthreads();
    if (t == 0) {
        const unsigned int r = atomicAdd(&g_scatdone, 1u);
        if (r == NSIDE - 1) {
            *(unsigned int*)&g_copydone = 0u;
            g_scatdone = 0u;
            for (int bb = 0; bb < Bn; ++bb)
                for (int s = 0; s < 12; ++s) g_bar[bb][s] = 0u;
        }
    }
}

// ---------------------------------------------------------------------------
extern "C" void kernel_launch(void* const* d_in, const int* in_sizes, int n_in,
                              void* d_out, int out_size) {
    const float* x     = (const float*)d_in[0];
    const float* edge  = (const float*)d_in[1];
    const float* w_adj = (const float*)d_in[2];
    const float* g_adj = (const float*)d_in[3];
    const float* b_adj = (const float*)d_in[4];
    const float* m_adj = (const float*)d_in[5];
    const float* v_adj = (const float*)d_in[6];
    const float* w_wg  = (const float*)d_in[7];
    const float* g_wg  = (const float*)d_in[8];
    const float* b_wg  = (const float*)d_in[9];
    const float* m_wg  = (const float*)d_in[10];
    const float* v_wg  = (const float*)d_in[11];
    float* out = (float*)d_out;

    // Single launch: role-split CTAs do copy + topk + gather + GEMMs + scatter.
    mega_kernel<<<NTOT, 512>>>((const float4*)x, (float4*)out,
                               x, edge,
                               w_adj, g_adj, b_adj, m_adj, v_adj,
                               w_wg, g_wg, b_wg, m_wg, v_wg,
                               out);
}